// round 5
// baseline (speedup 1.0000x reference)
#include <cuda_runtime.h>
#include <cstdint>

// Problem constants (fixed by the reference setup)
#define N_SAMPLES 4194304
#define N_RAYS    65536
#define SPT       8        // samples per thread (contiguous span)
#define TPB       256
#define BLK_SAMP  (TPB * SPT)          // 2048 samples per block
#define BLK_RGBF  (BLK_SAMP * 3)       // 6144 rgb floats per block
#define RGB_PAD   25                   // 24 floats/thread, stride 25 (conflict-free reads)

// ---------------------------------------------------------------------------
// Zero the output (harness poisons d_out to 0xAA before timing).
// ---------------------------------------------------------------------------
__global__ void zero_out_kernel(float4* __restrict__ out4, int n4) {
    int i = blockIdx.x * blockDim.x + threadIdx.x;
    if (i < n4) out4[i] = make_float4(0.f, 0.f, 0.f, 0.f);
}

// ---------------------------------------------------------------------------
// Sorted segment-sum with smem-staged rgb:
//  1. Block cooperatively loads its 24 KB rgb region with fully coalesced
//     float4 LDGs (16B lane stride -> minimal L1 wavefronts / clean HBM bursts)
//     and scatters into a padded per-owner smem layout.
//  2. Each thread reads its contiguous 24 rgb floats from smem (stride-25
//     scalar LDS -> bank-conflict-free) plus direct idx4/w4 LDGs (32B lane
//     stride -> already minimal wavefronts).
//  3. Run-length accumulate in registers; atomicAdd only at ray boundaries.
// ---------------------------------------------------------------------------
__global__ __launch_bounds__(TPB)
void integrate_color_kernel(const float4* __restrict__ rgb4,   // [N*3/4]
                            const float4* __restrict__ w4,     // [N/4]
                            const int4*   __restrict__ idx4,   // [N/4]
                            float*        __restrict__ out)    // [N_RAYS*3]
{
    __shared__ float s_rgb[TPB * RGB_PAD];   // 25600 B

    const int tid = threadIdx.x;
    const int blk = blockIdx.x;

    // ---- stage rgb: 1536 float4 per block, 6 per thread, coalesced ----
    {
        const long base4 = (long)blk * (BLK_RGBF / 4);
        #pragma unroll
        for (int c = 0; c < BLK_RGBF / (4 * TPB); ++c) {   // 6 iterations
            const int   lin  = c * TPB + tid;              // float4 slot in block
            const float4 v   = rgb4[base4 + lin];
            const int   g0   = lin * 4;                    // float offset in block
            const int   T    = g0 / 24;                    // owner thread
            const int   j0   = g0 % 24;                    // in {0,4,...,20}: never straddles
            float* dst = &s_rgb[T * RGB_PAD + j0];
            dst[0] = v.x; dst[1] = v.y; dst[2] = v.z; dst[3] = v.w;
        }
    }

    // ---- direct loads for weights + indices (already coalesced) ----
    int4   iv[SPT / 4];
    float4 wv[SPT / 4];
    const long vb = (long)blk * (BLK_SAMP / 4) + (long)tid * (SPT / 4);
    #pragma unroll
    for (int i = 0; i < SPT / 4; ++i) {
        iv[i] = idx4[vb + i];
        wv[i] = w4[vb + i];
    }

    __syncthreads();

    // ---- pull this thread's 24 rgb floats from smem (conflict-free) ----
    float col[SPT * 3];
    const float* src = &s_rgb[tid * RGB_PAD];
    #pragma unroll
    for (int j = 0; j < SPT * 3; ++j) col[j] = src[j];

    int   ridx[SPT];
    float wgt[SPT];
    #pragma unroll
    for (int i = 0; i < SPT / 4; ++i) {
        ridx[4*i + 0] = iv[i].x; ridx[4*i + 1] = iv[i].y;
        ridx[4*i + 2] = iv[i].z; ridx[4*i + 3] = iv[i].w;
        wgt[4*i + 0] = wv[i].x;  wgt[4*i + 1] = wv[i].y;
        wgt[4*i + 2] = wv[i].z;  wgt[4*i + 3] = wv[i].w;
    }

    // ---- run-length accumulate + boundary flush ----
    float ax = 0.f, ay = 0.f, az = 0.f;
    int cur = ridx[0];

    #pragma unroll
    for (int i = 0; i < SPT; ++i) {
        const int r = ridx[i];
        if (r != cur) {
            atomicAdd(&out[3 * cur + 0], ax);
            atomicAdd(&out[3 * cur + 1], ay);
            atomicAdd(&out[3 * cur + 2], az);
            cur = r;
            ax = ay = az = 0.f;
        }
        const float w = wgt[i];
        ax = fmaf(w, col[3*i + 0], ax);
        ay = fmaf(w, col[3*i + 1], ay);
        az = fmaf(w, col[3*i + 2], az);
    }
    atomicAdd(&out[3 * cur + 0], ax);
    atomicAdd(&out[3 * cur + 1], ay);
    atomicAdd(&out[3 * cur + 2], az);
}

// ---------------------------------------------------------------------------
// Harness entry. Inputs (metadata order): rgb_samples[f32 N*3],
// weights_samples[f32 N], ray_indices[i32 N], n_rays[i32 scalar].
// Output: f32 [N_RAYS*3].
// ---------------------------------------------------------------------------
extern "C" void kernel_launch(void* const* d_in, const int* in_sizes, int n_in,
                              void* d_out, int out_size)
{
    const float4* rgb4 = (const float4*)d_in[0];
    const float4* w4   = (const float4*)d_in[1];
    const int4*   idx4 = (const int4*)d_in[2];
    float*        out  = (float*)d_out;

    // zero the output: N_RAYS*3 = 196608 floats = 49152 float4
    const int n4 = (N_RAYS * 3) / 4;
    zero_out_kernel<<<(n4 + TPB - 1) / TPB, TPB>>>((float4*)d_out, n4);

    // scatter-accumulate: 4194304 / 2048 = 2048 blocks
    integrate_color_kernel<<<N_SAMPLES / BLK_SAMP, TPB>>>(rgb4, w4, idx4, out);
}

// round 9
// speedup vs baseline: 1.0152x; 1.0152x over previous
#include <cuda_runtime.h>
#include <cstdint>

// Problem constants (fixed by the reference setup)
#define N_SAMPLES 4194304
#define N_RAYS    65536
#define SPT       8        // samples per thread per iteration (contiguous)
#define TPB       256
#define TILE      (TPB * SPT)              // 2048 samples per tile
#define N_TILES   (N_SAMPLES / TILE)       // 2048 tiles
#define GRID      512                      // all resident in one wave (<= 592 slots)
#define TILES_PER_CTA (N_TILES / GRID)     // 4 contiguous tiles per CTA

// ---------------------------------------------------------------------------
// Zero the output (harness poisons d_out to 0xAA before timing).
// ---------------------------------------------------------------------------
__global__ void zero_out_kernel(float4* __restrict__ out4, int n4) {
    int i = blockIdx.x * blockDim.x + threadIdx.x;
    if (i < n4) out4[i] = make_float4(0.f, 0.f, 0.f, 0.f);
}

// ---------------------------------------------------------------------------
// Persistent single-wave sorted segment-sum. Each CTA streams a contiguous
// 8192-sample span (4 tiles). Per tile, each thread front-batches vector
// loads for its 8 contiguous samples, run-length accumulates in registers,
// and atomicAdds only at ray boundaries. No wave transitions: all 512 CTAs
// are resident for the whole kernel, keeping HBM load pressure continuous.
// ---------------------------------------------------------------------------
__global__ __launch_bounds__(TPB)
void integrate_color_kernel(const float4* __restrict__ rgb4,   // [N*3/4]
                            const float4* __restrict__ w4,     // [N/4]
                            const int4*   __restrict__ idx4,   // [N/4]
                            float*        __restrict__ out)    // [N_RAYS*3]
{
    const int tid = threadIdx.x;
    const int blk = blockIdx.x;

    #pragma unroll 1
    for (int it = 0; it < TILES_PER_CTA; ++it) {
        const int g = blk * TILES_PER_CTA + it;            // global tile index
        const int t = g * TPB + tid;                        // virtual thread id

        // ---- front-batched vector loads (max MLP) ----
        int4   iv[SPT / 4];            // 2 x int4
        float4 wv[SPT / 4];            // 2 x float4
        float4 cv[(SPT * 3) / 4];      // 6 x float4

        const long vb = (long)t * (SPT / 4);
        #pragma unroll
        for (int i = 0; i < SPT / 4; ++i) {
            iv[i] = idx4[vb + i];
            wv[i] = w4[vb + i];
        }
        const long cb = (long)t * ((SPT * 3) / 4);
        #pragma unroll
        for (int i = 0; i < (SPT * 3) / 4; ++i) {
            cv[i] = rgb4[cb + i];
        }

        // ---- unpack into flat register arrays ----
        int   ridx[SPT];
        float wgt[SPT];
        float col[SPT * 3];
        #pragma unroll
        for (int i = 0; i < SPT / 4; ++i) {
            ridx[4*i + 0] = iv[i].x; ridx[4*i + 1] = iv[i].y;
            ridx[4*i + 2] = iv[i].z; ridx[4*i + 3] = iv[i].w;
            wgt[4*i + 0] = wv[i].x;  wgt[4*i + 1] = wv[i].y;
            wgt[4*i + 2] = wv[i].z;  wgt[4*i + 3] = wv[i].w;
        }
        #pragma unroll
        for (int i = 0; i < (SPT * 3) / 4; ++i) {
            col[4*i + 0] = cv[i].x; col[4*i + 1] = cv[i].y;
            col[4*i + 2] = cv[i].z; col[4*i + 3] = cv[i].w;
        }

        // ---- run-length accumulate + boundary flush ----
        float ax = 0.f, ay = 0.f, az = 0.f;
        int cur = ridx[0];

        #pragma unroll
        for (int i = 0; i < SPT; ++i) {
            const int r = ridx[i];
            if (r != cur) {
                atomicAdd(&out[3 * cur + 0], ax);
                atomicAdd(&out[3 * cur + 1], ay);
                atomicAdd(&out[3 * cur + 2], az);
                cur = r;
                ax = ay = az = 0.f;
            }
            const float w = wgt[i];
            ax = fmaf(w, col[3*i + 0], ax);
            ay = fmaf(w, col[3*i + 1], ay);
            az = fmaf(w, col[3*i + 2], az);
        }
        atomicAdd(&out[3 * cur + 0], ax);
        atomicAdd(&out[3 * cur + 1], ay);
        atomicAdd(&out[3 * cur + 2], az);
    }
}

// ---------------------------------------------------------------------------
// Harness entry. Inputs (metadata order): rgb_samples[f32 N*3],
// weights_samples[f32 N], ray_indices[i32 N], n_rays[i32 scalar].
// Output: f32 [N_RAYS*3].
// ---------------------------------------------------------------------------
extern "C" void kernel_launch(void* const* d_in, const int* in_sizes, int n_in,
                              void* d_out, int out_size)
{
    const float4* rgb4 = (const float4*)d_in[0];
    const float4* w4   = (const float4*)d_in[1];
    const int4*   idx4 = (const int4*)d_in[2];
    float*        out  = (float*)d_out;

    // zero the output: N_RAYS*3 = 196608 floats = 49152 float4
    const int n4 = (N_RAYS * 3) / 4;
    zero_out_kernel<<<(n4 + TPB - 1) / TPB, TPB>>>((float4*)d_out, n4);

    // single-wave persistent scatter-accumulate
    integrate_color_kernel<<<GRID, TPB>>>(rgb4, w4, idx4, out);
}